// round 1
// baseline (speedup 1.0000x reference)
#include <cuda_runtime.h>

#define NN 100000
#define EE 1000000
#define GG 1024
#define FDIM 44
#define FEATD 1019

// ---------------- static scratch (no allocations allowed) ----------------
__device__ float    g_deg[NN];                    // degree, then dinv in-place
__device__ float    g_norm[EE];                   // dinv[src]*dinv[dst]
__device__ float    g_bufA[(size_t)NN * FDIM];    // layer1 / layer3 accumulators
__device__ float    g_bufB[(size_t)NN * 2 * FDIM];// layer2 accumulator
__device__ float    g_hW[(size_t)NN * 2 * FDIM];  // per-layer h@W staging
__device__ unsigned g_pool[GG * FDIM];            // max-pool as uint bits

// ---------------- degree / norm ----------------
__global__ void deg_init_k() {
    int i = blockIdx.x * blockDim.x + threadIdx.x;
    if (i < NN) g_deg[i] = 1.0f;   // self-loop contributes 1
}
__global__ void deg_count_k(const int* __restrict__ dst) {
    int e = blockIdx.x * blockDim.x + threadIdx.x;
    if (e < EE) atomicAdd(&g_deg[dst[e]], 1.0f);
}
__global__ void dinv_k() {
    int i = blockIdx.x * blockDim.x + threadIdx.x;
    if (i < NN) g_deg[i] = rsqrtf(g_deg[i]);
}
__global__ void norm_k(const int* __restrict__ src, const int* __restrict__ dst) {
    int e = blockIdx.x * blockDim.x + threadIdx.x;
    if (e < EE) g_norm[e] = g_deg[src[e]] * g_deg[dst[e]];
}

// ---------------- GEMM (+ fused bias & self-loop init of accumulator) ----------------
// hW[i,:] = act(in[i,:]) @ W ;  acc[i,:] = b + hW[i,:] * dinv[i]^2
template <int FIN, int FOUT, bool RELU, int TR>
__global__ void gemm_init_k(const float* __restrict__ in,
                            const float* __restrict__ W,
                            const float* __restrict__ b,
                            float* __restrict__ hW,
                            float* __restrict__ acc) {
    __shared__ __align__(16) float sWt[FOUT][FIN];  // transposed W: sWt[col][k]
    __shared__ __align__(16) float sIn[TR][FIN];
    __shared__ float sB[FOUT];
    const int nt = TR * FOUT;  // blockDim.x

    for (int i = threadIdx.x; i < FIN * FOUT; i += nt) {
        int k = i / FOUT, c = i - k * FOUT;
        sWt[c][k] = W[i];
    }
    for (int i = threadIdx.x; i < FOUT; i += nt) sB[i] = b[i];

    const int r = threadIdx.x / FOUT;
    const int c = threadIdx.x - r * FOUT;
    const int ntiles = (NN + TR - 1) / TR;

    for (int tile = blockIdx.x; tile < ntiles; tile += gridDim.x) {
        const int row0 = tile * TR;
        __syncthreads();
        for (int i = threadIdx.x; i < TR * FIN; i += nt) {
            int rr = i / FIN, kk = i - rr * FIN;
            int grow = row0 + rr;
            float v = (grow < NN) ? in[(size_t)grow * FIN + kk] : 0.0f;
            if (RELU) v = fmaxf(v, 0.0f);
            sIn[rr][kk] = v;
        }
        __syncthreads();
        const int grow = row0 + r;
        if (grow < NN) {
            float s = 0.0f;
#pragma unroll
            for (int k = 0; k < FIN; k += 4) {
                float4 a = *reinterpret_cast<const float4*>(&sIn[r][k]);
                float4 w = *reinterpret_cast<const float4*>(&sWt[c][k]);
                s += a.x * w.x + a.y * w.y + a.z * w.z + a.w * w.w;
            }
            size_t o = (size_t)grow * FOUT + c;
            hW[o] = s;
            float di = g_deg[grow];  // dinv
            acc[o] = sB[c] + s * di * di;
        }
    }
}

// ---------------- edge scatter: acc[dst,:] += hW[src,:]*norm ----------------
template <int FOUT>
__global__ void scatter_k(const int* __restrict__ src, const int* __restrict__ dst,
                          const float* __restrict__ hW, float* __restrict__ acc) {
    unsigned idx = blockIdx.x * blockDim.x + threadIdx.x;
    const unsigned total = (unsigned)EE * FOUT;
    if (idx >= total) return;
    unsigned e = idx / FOUT;
    unsigned f = idx - e * FOUT;
    int s = __ldg(&src[e]);
    int d = __ldg(&dst[e]);
    float v = __ldg(&hW[(size_t)s * FOUT + f]) * __ldg(&g_norm[e]);
    atomicAdd(&acc[(size_t)d * FOUT + f], v);
}

// ---------------- pooling ----------------
__global__ void pool_init_k() {
    int i = blockIdx.x * blockDim.x + threadIdx.x;
    if (i < GG * FDIM) g_pool[i] = 0u;  // relu'd values >= 0, so 0-bits is -inf here
}
__global__ void pool_k(const float* __restrict__ acc, const int* __restrict__ batch) {
    unsigned idx = blockIdx.x * blockDim.x + threadIdx.x;
    const unsigned total = (unsigned)NN * FDIM;
    if (idx >= total) return;
    unsigned i = idx / FDIM;
    unsigned f = idx - i * FDIM;
    float v = fmaxf(acc[idx], 0.0f);
    atomicMax(&g_pool[(unsigned)batch[i] * FDIM + f], __float_as_uint(v));
}

// ---------------- heads: out[g] = relu(pooled@Wg+bg) + relu(feat@Wf1+bf1)@Wf2+bf2 ----
__global__ void final_k(const float* __restrict__ feature,
                        const float* __restrict__ Wg,  const float* __restrict__ bg,
                        const float* __restrict__ Wf1, const float* __restrict__ bf1,
                        const float* __restrict__ Wf2, const float* __restrict__ bf2,
                        float* __restrict__ out) {
    constexpr int GPB = 4;  // graphs per block
    __shared__ float sf[GPB][1024];
    __shared__ float red1[GPB][4], red2[GPB][4];
    const int g0 = blockIdx.x * GPB;
    const int t = threadIdx.x;  // 128

#pragma unroll
    for (int q = 0; q < GPB; q++)
        for (int k = t; k < FEATD; k += 128)
            sf[q][k] = feature[(size_t)(g0 + q) * FEATD + k];
    __syncthreads();

    float acc[GPB];
    const float bb = bf1[t];
#pragma unroll
    for (int q = 0; q < GPB; q++) acc[q] = bb;
    for (int k = 0; k < FEATD; k++) {
        float w = __ldg(&Wf1[k * 128 + t]);
#pragma unroll
        for (int q = 0; q < GPB; q++) acc[q] += sf[q][k] * w;
    }
    const float w2 = Wf2[t];
    const float wg = (t < FDIM) ? Wg[t] : 0.0f;
    const int lane = t & 31, wid = t >> 5;
#pragma unroll
    for (int q = 0; q < GPB; q++) {
        float s2 = fmaxf(acc[q], 0.0f) * w2;
        float s1 = (t < FDIM) ? __uint_as_float(g_pool[(g0 + q) * FDIM + t]) * wg : 0.0f;
#pragma unroll
        for (int o = 16; o; o >>= 1) {
            s1 += __shfl_down_sync(0xffffffffu, s1, o);
            s2 += __shfl_down_sync(0xffffffffu, s2, o);
        }
        if (lane == 0) { red1[q][wid] = s1; red2[q][wid] = s2; }
    }
    __syncthreads();
    if (t < GPB) {
        int q = t;
        float a = red1[q][0] + red1[q][1] + red1[q][2] + red1[q][3];
        float c = red2[q][0] + red2[q][1] + red2[q][2] + red2[q][3];
        out[g0 + q] = fmaxf(a + bg[0], 0.0f) + c + bf2[0];
    }
}

// ---------------- launch ----------------
extern "C" void kernel_launch(void* const* d_in, const int* in_sizes, int n_in,
                              void* d_out, int out_size) {
    const float* x       = (const float*)d_in[0];
    const int*   ei      = (const int*)d_in[1];
    const int*   batch   = (const int*)d_in[2];
    const float* feature = (const float*)d_in[3];
    const float* W1 = (const float*)d_in[4];
    const float* b1 = (const float*)d_in[5];
    const float* W2 = (const float*)d_in[6];
    const float* b2 = (const float*)d_in[7];
    const float* W3 = (const float*)d_in[8];
    const float* b3 = (const float*)d_in[9];
    const float* Wg = (const float*)d_in[10];
    const float* bg = (const float*)d_in[11];
    const float* Wf1 = (const float*)d_in[12];
    const float* bf1 = (const float*)d_in[13];
    const float* Wf2 = (const float*)d_in[14];
    const float* bf2 = (const float*)d_in[15];
    float* out = (float*)d_out;

    const int* src = ei;        // edge_index[0]
    const int* dst = ei + EE;   // edge_index[1]

    void *pA, *pB, *pHW;
    cudaGetSymbolAddress(&pA, g_bufA);
    cudaGetSymbolAddress(&pB, g_bufB);
    cudaGetSymbolAddress(&pHW, g_hW);
    float* bufA = (float*)pA;
    float* bufB = (float*)pB;
    float* hW   = (float*)pHW;

    // degree / norm
    deg_init_k<<<(NN + 255) / 256, 256>>>();
    deg_count_k<<<(EE + 255) / 256, 256>>>(dst);
    dinv_k<<<(NN + 255) / 256, 256>>>();
    norm_k<<<(EE + 255) / 256, 256>>>(src, dst);

    // layer 1: x(44) -> bufA(44)
    gemm_init_k<44, 44, false, 8><<<592, 8 * 44>>>(x, W1, b1, hW, bufA);
    scatter_k<44><<<((unsigned)EE * 44 + 255) / 256, 256>>>(src, dst, hW, bufA);

    // layer 2: relu(bufA)(44) -> bufB(88)
    gemm_init_k<44, 88, true, 8><<<296, 8 * 88>>>(bufA, W2, b2, hW, bufB);
    scatter_k<88><<<((unsigned)EE * 88 + 255) / 256, 256>>>(src, dst, hW, bufB);

    // layer 3: relu(bufB)(88) -> bufA(44)
    gemm_init_k<88, 44, true, 8><<<592, 8 * 44>>>(bufB, W3, b3, hW, bufA);
    scatter_k<44><<<((unsigned)EE * 44 + 255) / 256, 256>>>(src, dst, hW, bufA);

    // max pool (relu fused)
    pool_init_k<<<(GG * FDIM + 255) / 256, 256>>>();
    pool_k<<<((unsigned)NN * FDIM + 255) / 256, 256>>>(bufA, batch);

    // heads
    final_k<<<GG / 4, 128>>>(feature, Wg, bg, Wf1, bf1, Wf2, bf2, out);
}

// round 3
// speedup vs baseline: 1.6854x; 1.6854x over previous
#include <cuda_runtime.h>

#define NN 100000
#define EE 1000000
#define GG 1024
#define FDIM 44
#define FEATD 1019
#define NB_SCAN ((NN + 1023) / 1024)   // 98

// ---------------- static scratch ----------------
__device__ int      g_cnt[NN];          // in-degree (without self loop)
__device__ int      g_off[NN];          // CSR row start (exclusive scan of cnt)
__device__ int      g_cur[NN];          // binning cursor
__device__ int      g_bsum[128];        // block sums for scan
__device__ float    g_dinv[NN];         // rsqrt(deg)
__device__ float2   g_csr[EE];          // {src (bits), norm} grouped by dst
__device__ float    g_bufA[(size_t)NN * FDIM];     // layer1 output
__device__ float    g_bufB[(size_t)NN * 2 * FDIM]; // layer2 output
__device__ float    g_hW[(size_t)NN * 2 * FDIM];   // per-layer h@W staging
__device__ unsigned g_pool[GG * FDIM];  // max-pool as uint bits

// ---------------- histogram ----------------
__global__ void hist_init_k() {
    int i = blockIdx.x * blockDim.x + threadIdx.x;
    if (i < NN) g_cnt[i] = 0;
}
__global__ void hist_k(const int* __restrict__ dst) {
    int e = blockIdx.x * blockDim.x + threadIdx.x;
    if (e < EE) atomicAdd(&g_cnt[dst[e]], 1);
}

// ---------------- exclusive scan (3 kernels) ----------------
__global__ void scan1_k() {   // per-block exclusive scan + block totals
    __shared__ int sh[1024];
    int gi = blockIdx.x * 1024 + threadIdx.x;
    int v = (gi < NN) ? g_cnt[gi] : 0;
    int acc = v;
    sh[threadIdx.x] = acc;
    __syncthreads();
#pragma unroll
    for (int o = 1; o < 1024; o <<= 1) {
        int t = (threadIdx.x >= o) ? sh[threadIdx.x - o] : 0;
        __syncthreads();
        acc += t;
        sh[threadIdx.x] = acc;
        __syncthreads();
    }
    if (gi < NN) g_off[gi] = acc - v;          // exclusive within block
    if (threadIdx.x == 1023) g_bsum[blockIdx.x] = acc;
}
__global__ void scan2_k() {   // 1 block, exclusive scan of 98 block sums
    __shared__ int sh[128];
    int v = (threadIdx.x < NB_SCAN) ? g_bsum[threadIdx.x] : 0;
    int acc = v;
    sh[threadIdx.x] = acc;
    __syncthreads();
#pragma unroll
    for (int o = 1; o < 128; o <<= 1) {
        int t = (threadIdx.x >= o) ? sh[threadIdx.x - o] : 0;
        __syncthreads();
        acc += t;
        sh[threadIdx.x] = acc;
        __syncthreads();
    }
    if (threadIdx.x < NB_SCAN) g_bsum[threadIdx.x] = acc - v;  // exclusive
}
__global__ void scan3_k() {   // add block offsets; compute dinv; reset cursors
    int i = blockIdx.x * blockDim.x + threadIdx.x;
    if (i < NN) {
        g_off[i] += g_bsum[i >> 10];
        g_dinv[i] = rsqrtf((float)g_cnt[i] + 1.0f);  // +1 self loop
        g_cur[i] = 0;
    }
}

// ---------------- edge binning: csr[pos] = {src, dinv[s]*dinv[d]} ----------------
__global__ void bin_k(const int* __restrict__ src, const int* __restrict__ dst) {
    int e = blockIdx.x * blockDim.x + threadIdx.x;
    if (e >= EE) return;
    int s = __ldg(&src[e]);
    int d = __ldg(&dst[e]);
    int pos = g_off[d] + atomicAdd(&g_cur[d], 1);
    g_csr[pos] = make_float2(__int_as_float(s), g_dinv[s] * g_dinv[d]);
}

// ---------------- GEMM: hW = act(in) @ W ----------------
template <int FIN, int FOUT, bool RELU, int TR>
__global__ void gemm_k(const float* __restrict__ in,
                       const float* __restrict__ W,
                       float* __restrict__ hW) {
    __shared__ __align__(16) float sWt[FOUT][FIN];  // transposed W
    __shared__ __align__(16) float sIn[TR][FIN];
    const int nt = TR * FOUT;

    for (int i = threadIdx.x; i < FIN * FOUT; i += nt) {
        int k = i / FOUT, c = i - k * FOUT;
        sWt[c][k] = W[i];
    }
    const int r = threadIdx.x / FOUT;
    const int c = threadIdx.x - r * FOUT;
    const int ntiles = (NN + TR - 1) / TR;

    for (int tile = blockIdx.x; tile < ntiles; tile += gridDim.x) {
        const int row0 = tile * TR;
        __syncthreads();
        for (int i = threadIdx.x; i < TR * FIN; i += nt) {
            int rr = i / FIN, kk = i - rr * FIN;
            int grow = row0 + rr;
            float v = (grow < NN) ? in[(size_t)grow * FIN + kk] : 0.0f;
            if (RELU) v = fmaxf(v, 0.0f);
            sIn[rr][kk] = v;
        }
        __syncthreads();
        const int grow = row0 + r;
        if (grow < NN) {
            float s = 0.0f;
#pragma unroll
            for (int k = 0; k < FIN; k += 4) {
                float4 a = *reinterpret_cast<const float4*>(&sIn[r][k]);
                float4 w = *reinterpret_cast<const float4*>(&sWt[c][k]);
                s += a.x * w.x + a.y * w.y + a.z * w.z + a.w * w.w;
            }
            hW[(size_t)grow * FOUT + c] = s;
        }
    }
}

// ---------------- CSR gather: out[n,:] = b + hW[n,:]*dinv^2 + sum_in hW[s,:]*norm ----
template <int F, bool POOL>
__global__ void gather_k(const float* __restrict__ hW,
                         const float* __restrict__ b,
                         float* __restrict__ out,
                         const int* __restrict__ batch) {
    constexpr int Q = F / 4;
    unsigned idx = blockIdx.x * blockDim.x + threadIdx.x;
    if (idx >= (unsigned)NN * Q) return;
    int node = idx / Q;
    int q = idx - node * Q;

    const float4* __restrict__ hw4 = reinterpret_cast<const float4*>(hW);
    float4 a = __ldg(&hw4[(size_t)node * Q + q]);
    float4 bb = __ldg(&reinterpret_cast<const float4*>(b)[q]);
    float di = g_dinv[node];
    float sc = di * di;
    float4 acc;
    acc.x = bb.x + a.x * sc;
    acc.y = bb.y + a.y * sc;
    acc.z = bb.z + a.z * sc;
    acc.w = bb.w + a.w * sc;

    int beg = g_off[node];
    int n = g_cnt[node];
    for (int j = 0; j < n; j++) {
        float2 c = __ldg(&g_csr[beg + j]);
        int s = __float_as_int(c.x);
        float4 v = __ldg(&hw4[(size_t)s * Q + q]);
        acc.x += v.x * c.y;
        acc.y += v.y * c.y;
        acc.z += v.z * c.y;
        acc.w += v.w * c.y;
    }

    if (POOL) {
        unsigned base = (unsigned)__ldg(&batch[node]) * F + q * 4;
        atomicMax(&g_pool[base + 0], __float_as_uint(fmaxf(acc.x, 0.0f)));
        atomicMax(&g_pool[base + 1], __float_as_uint(fmaxf(acc.y, 0.0f)));
        atomicMax(&g_pool[base + 2], __float_as_uint(fmaxf(acc.z, 0.0f)));
        atomicMax(&g_pool[base + 3], __float_as_uint(fmaxf(acc.w, 0.0f)));
    } else {
        reinterpret_cast<float4*>(out)[(size_t)node * Q + q] = acc;
    }
}

// ---------------- pooling init ----------------
__global__ void pool_init_k() {
    int i = blockIdx.x * blockDim.x + threadIdx.x;
    if (i < GG * FDIM) g_pool[i] = 0u;  // relu'd values >= 0
}

// ---------------- heads ----------------
__global__ void final_k(const float* __restrict__ feature,
                        const float* __restrict__ Wg,  const float* __restrict__ bg,
                        const float* __restrict__ Wf1, const float* __restrict__ bf1,
                        const float* __restrict__ Wf2, const float* __restrict__ bf2,
                        float* __restrict__ out) {
    constexpr int GPB = 4;
    __shared__ float sf[GPB][1024];
    __shared__ float red1[GPB][4], red2[GPB][4];
    const int g0 = blockIdx.x * GPB;
    const int t = threadIdx.x;  // 128

#pragma unroll
    for (int q = 0; q < GPB; q++)
        for (int k = t; k < FEATD; k += 128)
            sf[q][k] = feature[(size_t)(g0 + q) * FEATD + k];
    __syncthreads();

    float acc[GPB];
    const float bb = bf1[t];
#pragma unroll
    for (int q = 0; q < GPB; q++) acc[q] = bb;
    for (int k = 0; k < FEATD; k++) {
        float w = __ldg(&Wf1[k * 128 + t]);
#pragma unroll
        for (int q = 0; q < GPB; q++) acc[q] += sf[q][k] * w;
    }
    const float w2 = Wf2[t];
    const float wg = (t < FDIM) ? Wg[t] : 0.0f;
    const int lane = t & 31, wid = t >> 5;
#pragma unroll
    for (int q = 0; q < GPB; q++) {
        float s2 = fmaxf(acc[q], 0.0f) * w2;
        float s1 = (t < FDIM) ? __uint_as_float(g_pool[(g0 + q) * FDIM + t]) * wg : 0.0f;
#pragma unroll
        for (int o = 16; o; o >>= 1) {
            s1 += __shfl_down_sync(0xffffffffu, s1, o);
            s2 += __shfl_down_sync(0xffffffffu, s2, o);
        }
        if (lane == 0) { red1[q][wid] = s1; red2[q][wid] = s2; }
    }
    __syncthreads();
    if (t < GPB) {
        int q = t;
        float a = red1[q][0] + red1[q][1] + red1[q][2] + red1[q][3];
        float c = red2[q][0] + red2[q][1] + red2[q][2] + red2[q][3];
        out[g0 + q] = fmaxf(a + bg[0], 0.0f) + c + bf2[0];
    }
}

// ---------------- launch ----------------
extern "C" void kernel_launch(void* const* d_in, const int* in_sizes, int n_in,
                              void* d_out, int out_size) {
    const float* x       = (const float*)d_in[0];
    const int*   ei      = (const int*)d_in[1];
    const int*   batch   = (const int*)d_in[2];
    const float* feature = (const float*)d_in[3];
    const float* W1 = (const float*)d_in[4];
    const float* b1 = (const float*)d_in[5];
    const float* W2 = (const float*)d_in[6];
    const float* b2 = (const float*)d_in[7];
    const float* W3 = (const float*)d_in[8];
    const float* b3 = (const float*)d_in[9];
    const float* Wg = (const float*)d_in[10];
    const float* bg = (const float*)d_in[11];
    const float* Wf1 = (const float*)d_in[12];
    const float* bf1 = (const float*)d_in[13];
    const float* Wf2 = (const float*)d_in[14];
    const float* bf2 = (const float*)d_in[15];
    float* out = (float*)d_out;

    const int* src = ei;        // edge_index[0]
    const int* dst = ei + EE;   // edge_index[1]

    void *pA, *pB, *pHW;
    cudaGetSymbolAddress(&pA, g_bufA);
    cudaGetSymbolAddress(&pB, g_bufB);
    cudaGetSymbolAddress(&pHW, g_hW);
    float* bufA = (float*)pA;
    float* bufB = (float*)pB;
    float* hW   = (float*)pHW;

    // CSR build (once; reused by all 3 layers)
    hist_init_k<<<(NN + 255) / 256, 256>>>();
    hist_k<<<(EE + 255) / 256, 256>>>(dst);
    scan1_k<<<NB_SCAN, 1024>>>();
    scan2_k<<<1, 128>>>();
    scan3_k<<<(NN + 255) / 256, 256>>>();
    bin_k<<<(EE + 255) / 256, 256>>>(src, dst);
    pool_init_k<<<(GG * FDIM + 255) / 256, 256>>>();

    // layer 1: x(44) -> bufA(44)
    gemm_k<44, 44, false, 8><<<592, 8 * 44>>>(x, W1, hW);
    gather_k<44, false><<<((unsigned)NN * 11 + 255) / 256, 256>>>(hW, b1, bufA, batch);

    // layer 2: relu(bufA)(44) -> bufB(88)
    gemm_k<44, 88, true, 8><<<296, 8 * 88>>>(bufA, W2, hW);
    gather_k<88, false><<<((unsigned)NN * 22 + 255) / 256, 256>>>(hW, b2, bufB, batch);

    // layer 3: relu(bufB)(88) -> pool (fused)
    gemm_k<88, 44, true, 8><<<592, 8 * 44>>>(bufB, W3, hW);
    gather_k<44, true><<<((unsigned)NN * 11 + 255) / 256, 256>>>(hW, b3, nullptr, batch);

    // heads
    final_k<<<GG / 4, 128>>>(feature, Wg, bg, Wf1, bf1, Wf2, bf2, out);
}

// round 4
// speedup vs baseline: 1.8301x; 1.0859x over previous
#include <cuda_runtime.h>

#define NN 100000
#define EE 1000000
#define GG 1024
#define FDIM 44
#define FEATD 1019
#define NB_SCAN ((NN + 1023) / 1024)   // 98

// ---------------- static scratch ----------------
__device__ int      g_cnt[NN];          // in-degree (without self loop)
__device__ int      g_off[NN];          // CSR row start
__device__ int      g_cur[NN];          // binning cursor
__device__ int      g_bsum[128];        // block sums for scan
__device__ float    g_dinv[NN];         // rsqrt(deg)
__device__ float2   g_csr[EE];          // {src (bits), norm} grouped by dst
__device__ float    g_bufA[(size_t)NN * FDIM];     // layer1 activation
__device__ float    g_bufB[(size_t)NN * 2 * FDIM]; // layer2 activation
__device__ float    g_tmp[(size_t)NN * FDIM];      // agg staging / hW3
__device__ unsigned g_pool[GG * FDIM];  // max-pool as uint bits

// ---------------- histogram ----------------
__global__ void hist_init_k() {
    int i = blockIdx.x * blockDim.x + threadIdx.x;
    if (i < NN) g_cnt[i] = 0;
}
__global__ void hist_k(const int* __restrict__ dst) {
    int e = blockIdx.x * blockDim.x + threadIdx.x;
    if (e < EE) atomicAdd(&g_cnt[dst[e]], 1);
}

// ---------------- exclusive scan ----------------
__global__ void scan1_k() {
    __shared__ int sh[1024];
    int gi = blockIdx.x * 1024 + threadIdx.x;
    int v = (gi < NN) ? g_cnt[gi] : 0;
    int acc = v;
    sh[threadIdx.x] = acc;
    __syncthreads();
#pragma unroll
    for (int o = 1; o < 1024; o <<= 1) {
        int t = (threadIdx.x >= o) ? sh[threadIdx.x - o] : 0;
        __syncthreads();
        acc += t;
        sh[threadIdx.x] = acc;
        __syncthreads();
    }
    if (gi < NN) g_off[gi] = acc - v;
    if (threadIdx.x == 1023) g_bsum[blockIdx.x] = acc;
}
__global__ void scan2_k() {
    __shared__ int sh[128];
    int v = (threadIdx.x < NB_SCAN) ? g_bsum[threadIdx.x] : 0;
    int acc = v;
    sh[threadIdx.x] = acc;
    __syncthreads();
#pragma unroll
    for (int o = 1; o < 128; o <<= 1) {
        int t = (threadIdx.x >= o) ? sh[threadIdx.x - o] : 0;
        __syncthreads();
        acc += t;
        sh[threadIdx.x] = acc;
        __syncthreads();
    }
    if (threadIdx.x < NB_SCAN) g_bsum[threadIdx.x] = acc - v;
}
__global__ void scan3_k() {
    int i = blockIdx.x * blockDim.x + threadIdx.x;
    if (i < NN) {
        g_off[i] += g_bsum[i >> 10];
        g_dinv[i] = rsqrtf((float)g_cnt[i] + 1.0f);
        g_cur[i] = 0;
    }
}

// ---------------- edge binning ----------------
__global__ void bin_k(const int* __restrict__ src, const int* __restrict__ dst) {
    int e = blockIdx.x * blockDim.x + threadIdx.x;
    if (e >= EE) return;
    int s = __ldg(&src[e]);
    int d = __ldg(&dst[e]);
    int pos = g_off[d] + atomicAdd(&g_cur[d], 1);
    g_csr[pos] = make_float2(__int_as_float(s), g_dinv[s] * g_dinv[d]);
}

// ---------------- warp-per-node aggregation over 44 features ----------------
// out[n,:] = (b +) in[n,:]*dinv^2 + sum_{(s,w) in csr[n]} in[s,:]*w  (+relu+pool)
template <bool POOL>
__global__ __launch_bounds__(128) void agg44_k(const float* __restrict__ in,
                                               const float* __restrict__ b,
                                               float* __restrict__ out,
                                               const int* __restrict__ batch) {
    int node = blockIdx.x * 4 + (threadIdx.x >> 5);
    if (node >= NN) return;
    const int lane = threadIdx.x & 31;
    const bool hi = lane < (FDIM - 32);   // 12 lanes for chunk 1

    const float* __restrict__ row = in + (size_t)node * FDIM;
    float di = g_dinv[node];
    float sc = di * di;
    float acc0 = __ldg(&row[lane]) * sc;
    float acc1 = hi ? __ldg(&row[32 + lane]) * sc : 0.0f;

    const int n = g_cnt[node];
    const float2* __restrict__ csr = g_csr + g_off[node];

    int j = 0;
    for (; j + 4 <= n; j += 4) {
        float2 c0 = __ldg(&csr[j + 0]);
        float2 c1 = __ldg(&csr[j + 1]);
        float2 c2 = __ldg(&csr[j + 2]);
        float2 c3 = __ldg(&csr[j + 3]);
        const float* r0 = in + (size_t)__float_as_int(c0.x) * FDIM;
        const float* r1 = in + (size_t)__float_as_int(c1.x) * FDIM;
        const float* r2 = in + (size_t)__float_as_int(c2.x) * FDIM;
        const float* r3 = in + (size_t)__float_as_int(c3.x) * FDIM;
        float v00 = __ldg(&r0[lane]);
        float v10 = __ldg(&r1[lane]);
        float v20 = __ldg(&r2[lane]);
        float v30 = __ldg(&r3[lane]);
        float v01 = hi ? __ldg(&r0[32 + lane]) : 0.0f;
        float v11 = hi ? __ldg(&r1[32 + lane]) : 0.0f;
        float v21 = hi ? __ldg(&r2[32 + lane]) : 0.0f;
        float v31 = hi ? __ldg(&r3[32 + lane]) : 0.0f;
        acc0 += v00 * c0.y + v10 * c1.y + v20 * c2.y + v30 * c3.y;
        acc1 += v01 * c0.y + v11 * c1.y + v21 * c2.y + v31 * c3.y;
    }
    for (; j < n; j++) {
        float2 c = __ldg(&csr[j]);
        const float* r = in + (size_t)__float_as_int(c.x) * FDIM;
        acc0 += __ldg(&r[lane]) * c.y;
        if (hi) acc1 += __ldg(&r[32 + lane]) * c.y;
    }

    if (POOL) {
        acc0 = fmaxf(acc0 + __ldg(&b[lane]), 0.0f);
        unsigned gbase = (unsigned)__ldg(&batch[node]) * FDIM;
        atomicMax(&g_pool[gbase + lane], __float_as_uint(acc0));
        if (hi) {
            acc1 = fmaxf(acc1 + __ldg(&b[32 + lane]), 0.0f);
            atomicMax(&g_pool[gbase + 32 + lane], __float_as_uint(acc1));
        }
    } else {
        out[(size_t)node * FDIM + lane] = acc0;
        if (hi) out[(size_t)node * FDIM + 32 + lane] = acc1;
    }
}

// ---------------- GEMM: out = (relu(in@W + b)) or (in@W) ----------------
template <int FIN, int FOUT, bool EPI, int TR>
__global__ void gemm_k(const float* __restrict__ in,
                       const float* __restrict__ W,
                       const float* __restrict__ b,
                       float* __restrict__ out) {
    __shared__ __align__(16) float sWt[FOUT][FIN];  // transposed W
    __shared__ __align__(16) float sIn[TR][FIN];
    __shared__ float sB[FOUT];
    const int nt = TR * FOUT;

    for (int i = threadIdx.x; i < FIN * FOUT; i += nt) {
        int k = i / FOUT, c = i - k * FOUT;
        sWt[c][k] = W[i];
    }
    if (EPI)
        for (int i = threadIdx.x; i < FOUT; i += nt) sB[i] = b[i];

    const int r = threadIdx.x / FOUT;
    const int c = threadIdx.x - r * FOUT;
    const int ntiles = (NN + TR - 1) / TR;

    for (int tile = blockIdx.x; tile < ntiles; tile += gridDim.x) {
        const int row0 = tile * TR;
        __syncthreads();
        for (int i = threadIdx.x; i < TR * FIN; i += nt) {
            int rr = i / FIN, kk = i - rr * FIN;
            int grow = row0 + rr;
            sIn[rr][kk] = (grow < NN) ? in[(size_t)grow * FIN + kk] : 0.0f;
        }
        __syncthreads();
        const int grow = row0 + r;
        if (grow < NN) {
            float s = 0.0f;
#pragma unroll
            for (int k = 0; k < FIN; k += 4) {
                float4 a = *reinterpret_cast<const float4*>(&sIn[r][k]);
                float4 w = *reinterpret_cast<const float4*>(&sWt[c][k]);
                s += a.x * w.x + a.y * w.y + a.z * w.z + a.w * w.w;
            }
            if (EPI) s = fmaxf(s + sB[c], 0.0f);
            out[(size_t)grow * FOUT + c] = s;
        }
    }
}

// ---------------- pooling init ----------------
__global__ void pool_init_k() {
    int i = blockIdx.x * blockDim.x + threadIdx.x;
    if (i < GG * FDIM) g_pool[i] = 0u;
}

// ---------------- heads ----------------
__global__ void final_k(const float* __restrict__ feature,
                        const float* __restrict__ Wg,  const float* __restrict__ bg,
                        const float* __restrict__ Wf1, const float* __restrict__ bf1,
                        const float* __restrict__ Wf2, const float* __restrict__ bf2,
                        float* __restrict__ out) {
    constexpr int GPB = 4;
    __shared__ float sf[GPB][1024];
    __shared__ float red1[GPB][4], red2[GPB][4];
    const int g0 = blockIdx.x * GPB;
    const int t = threadIdx.x;  // 128

#pragma unroll
    for (int q = 0; q < GPB; q++)
        for (int k = t; k < FEATD; k += 128)
            sf[q][k] = feature[(size_t)(g0 + q) * FEATD + k];
    __syncthreads();

    float acc[GPB];
    const float bb = bf1[t];
#pragma unroll
    for (int q = 0; q < GPB; q++) acc[q] = bb;
    for (int k = 0; k < FEATD; k++) {
        float w = __ldg(&Wf1[k * 128 + t]);
#pragma unroll
        for (int q = 0; q < GPB; q++) acc[q] += sf[q][k] * w;
    }
    const float w2 = Wf2[t];
    const float wg = (t < FDIM) ? Wg[t] : 0.0f;
    const int lane = t & 31, wid = t >> 5;
#pragma unroll
    for (int q = 0; q < GPB; q++) {
        float s2 = fmaxf(acc[q], 0.0f) * w2;
        float s1 = (t < FDIM) ? __uint_as_float(g_pool[(g0 + q) * FDIM + t]) * wg : 0.0f;
#pragma unroll
        for (int o = 16; o; o >>= 1) {
            s1 += __shfl_down_sync(0xffffffffu, s1, o);
            s2 += __shfl_down_sync(0xffffffffu, s2, o);
        }
        if (lane == 0) { red1[q][wid] = s1; red2[q][wid] = s2; }
    }
    __syncthreads();
    if (t < GPB) {
        int q = t;
        float a = red1[q][0] + red1[q][1] + red1[q][2] + red1[q][3];
        float c = red2[q][0] + red2[q][1] + red2[q][2] + red2[q][3];
        out[g0 + q] = fmaxf(a + bg[0], 0.0f) + c + bf2[0];
    }
}

// ---------------- launch ----------------
extern "C" void kernel_launch(void* const* d_in, const int* in_sizes, int n_in,
                              void* d_out, int out_size) {
    const float* x       = (const float*)d_in[0];
    const int*   ei      = (const int*)d_in[1];
    const int*   batch   = (const int*)d_in[2];
    const float* feature = (const float*)d_in[3];
    const float* W1 = (const float*)d_in[4];
    const float* b1 = (const float*)d_in[5];
    const float* W2 = (const float*)d_in[6];
    const float* b2 = (const float*)d_in[7];
    const float* W3 = (const float*)d_in[8];
    const float* b3 = (const float*)d_in[9];
    const float* Wg = (const float*)d_in[10];
    const float* bg = (const float*)d_in[11];
    const float* Wf1 = (const float*)d_in[12];
    const float* bf1 = (const float*)d_in[13];
    const float* Wf2 = (const float*)d_in[14];
    const float* bf2 = (const float*)d_in[15];
    float* out = (float*)d_out;

    const int* src = ei;        // edge_index[0]
    const int* dst = ei + EE;   // edge_index[1]

    void *pA, *pB, *pT;
    cudaGetSymbolAddress(&pA, g_bufA);
    cudaGetSymbolAddress(&pB, g_bufB);
    cudaGetSymbolAddress(&pT, g_tmp);
    float* bufA = (float*)pA;
    float* bufB = (float*)pB;
    float* tmp  = (float*)pT;

    const int AGG_GRID = (NN + 3) / 4;

    // CSR build (reused by all 3 layers)
    hist_init_k<<<(NN + 255) / 256, 256>>>();
    hist_k<<<(EE + 255) / 256, 256>>>(dst);
    scan1_k<<<NB_SCAN, 1024>>>();
    scan2_k<<<1, 128>>>();
    scan3_k<<<(NN + 255) / 256, 256>>>();
    bin_k<<<(EE + 255) / 256, 256>>>(src, dst);
    pool_init_k<<<(GG * FDIM + 255) / 256, 256>>>();

    // layer 1 (aggregate-first): tmp = A_norm @ x ; bufA = relu(tmp@W1+b1)
    agg44_k<false><<<AGG_GRID, 128>>>(x, nullptr, tmp, nullptr);
    gemm_k<44, 44, true, 8><<<592, 8 * 44>>>(tmp, W1, b1, bufA);

    // layer 2 (aggregate-first): tmp = A_norm @ bufA ; bufB = relu(tmp@W2+b2)
    agg44_k<false><<<AGG_GRID, 128>>>(bufA, nullptr, tmp, nullptr);
    gemm_k<44, 88, true, 8><<<296, 8 * 88>>>(tmp, W2, b2, bufB);

    // layer 3 (transform-first): tmp = bufB@W3 ; pool(relu(A_norm@tmp + b3))
    gemm_k<88, 44, false, 8><<<592, 8 * 44>>>(bufB, W3, nullptr, tmp);
    agg44_k<true><<<AGG_GRID, 128>>>(tmp, b3, nullptr, batch);

    // heads
    final_k<<<GG / 4, 128>>>(feature, Wg, bg, Wf1, bf1, Wf2, bf2, out);
}

// round 6
// speedup vs baseline: 2.0298x; 1.1091x over previous
#include <cuda_runtime.h>

#define NN 100000
#define EE 1000000
#define GG 1024
#define FDIM 44
#define FEATD 1019
#define NB_SCAN ((NN + 1023) / 1024)   // 98

// ---------------- static scratch ----------------
__device__ int      g_cnt[NN];
__device__ int      g_off[NN];
__device__ int      g_cur[NN];
__device__ int      g_bsum[128];
__device__ float    g_dinv[NN];
__device__ float2   g_csr[EE];
__device__ __align__(16) float g_bufA[(size_t)NN * FDIM];
__device__ __align__(16) float g_bufB[(size_t)NN * 2 * FDIM];
__device__ __align__(16) float g_tmp[(size_t)NN * FDIM];
__device__ unsigned g_pool[GG * FDIM];

// ---------------- histogram ----------------
__global__ void hist_init_k() {
    int i = blockIdx.x * blockDim.x + threadIdx.x;
    if (i < NN) g_cnt[i] = 0;
}
__global__ void hist_k(const int* __restrict__ dst) {
    int e = blockIdx.x * blockDim.x + threadIdx.x;
    if (e < EE) atomicAdd(&g_cnt[dst[e]], 1);
}

// ---------------- exclusive scan ----------------
__global__ void scan1_k() {
    __shared__ int sh[1024];
    int gi = blockIdx.x * 1024 + threadIdx.x;
    int v = (gi < NN) ? g_cnt[gi] : 0;
    int acc = v;
    sh[threadIdx.x] = acc;
    __syncthreads();
#pragma unroll
    for (int o = 1; o < 1024; o <<= 1) {
        int t = (threadIdx.x >= o) ? sh[threadIdx.x - o] : 0;
        __syncthreads();
        acc += t;
        sh[threadIdx.x] = acc;
        __syncthreads();
    }
    if (gi < NN) g_off[gi] = acc - v;
    if (threadIdx.x == 1023) g_bsum[blockIdx.x] = acc;
}
__global__ void scan2_k() {
    __shared__ int sh[128];
    int v = (threadIdx.x < NB_SCAN) ? g_bsum[threadIdx.x] : 0;
    int acc = v;
    sh[threadIdx.x] = acc;
    __syncthreads();
#pragma unroll
    for (int o = 1; o < 128; o <<= 1) {
        int t = (threadIdx.x >= o) ? sh[threadIdx.x - o] : 0;
        __syncthreads();
        acc += t;
        sh[threadIdx.x] = acc;
        __syncthreads();
    }
    if (threadIdx.x < NB_SCAN) g_bsum[threadIdx.x] = acc - v;
}
__global__ void scan3_k() {
    int i = blockIdx.x * blockDim.x + threadIdx.x;
    if (i < NN) {
        g_off[i] += g_bsum[i >> 10];
        g_dinv[i] = rsqrtf((float)g_cnt[i] + 1.0f);
        g_cur[i] = 0;
    }
}

// ---------------- edge binning ----------------
__global__ void bin_k(const int* __restrict__ src, const int* __restrict__ dst) {
    int e = blockIdx.x * blockDim.x + threadIdx.x;
    if (e >= EE) return;
    int s = __ldg(&src[e]);
    int d = __ldg(&dst[e]);
    int pos = g_off[d] + atomicAdd(&g_cur[d], 1);
    g_csr[pos] = make_float2(__int_as_float(s), g_dinv[s] * g_dinv[d]);
}

// ---------------- warp-per-node aggregation over 44 features ----------------
template <bool POOL>
__global__ __launch_bounds__(128) void agg44_k(const float* __restrict__ in,
                                               const float* __restrict__ b,
                                               float* __restrict__ out,
                                               const int* __restrict__ batch) {
    int node = blockIdx.x * 4 + (threadIdx.x >> 5);
    if (node >= NN) return;
    const int lane = threadIdx.x & 31;
    const bool hi = lane < (FDIM - 32);

    const float* __restrict__ row = in + (size_t)node * FDIM;
    float di = g_dinv[node];
    float sc = di * di;
    float acc0 = __ldg(&row[lane]) * sc;
    float acc1 = hi ? __ldg(&row[32 + lane]) * sc : 0.0f;

    const int n = g_cnt[node];
    const float2* __restrict__ csr = g_csr + g_off[node];

    int j = 0;
    for (; j + 4 <= n; j += 4) {
        float2 c0 = __ldg(&csr[j + 0]);
        float2 c1 = __ldg(&csr[j + 1]);
        float2 c2 = __ldg(&csr[j + 2]);
        float2 c3 = __ldg(&csr[j + 3]);
        const float* r0 = in + (size_t)__float_as_int(c0.x) * FDIM;
        const float* r1 = in + (size_t)__float_as_int(c1.x) * FDIM;
        const float* r2 = in + (size_t)__float_as_int(c2.x) * FDIM;
        const float* r3 = in + (size_t)__float_as_int(c3.x) * FDIM;
        float v00 = __ldg(&r0[lane]);
        float v10 = __ldg(&r1[lane]);
        float v20 = __ldg(&r2[lane]);
        float v30 = __ldg(&r3[lane]);
        float v01 = hi ? __ldg(&r0[32 + lane]) : 0.0f;
        float v11 = hi ? __ldg(&r1[32 + lane]) : 0.0f;
        float v21 = hi ? __ldg(&r2[32 + lane]) : 0.0f;
        float v31 = hi ? __ldg(&r3[32 + lane]) : 0.0f;
        acc0 += v00 * c0.y + v10 * c1.y + v20 * c2.y + v30 * c3.y;
        acc1 += v01 * c0.y + v11 * c1.y + v21 * c2.y + v31 * c3.y;
    }
    for (; j < n; j++) {
        float2 c = __ldg(&csr[j]);
        const float* r = in + (size_t)__float_as_int(c.x) * FDIM;
        acc0 += __ldg(&r[lane]) * c.y;
        if (hi) acc1 += __ldg(&r[32 + lane]) * c.y;
    }

    if (POOL) {
        acc0 = fmaxf(acc0 + __ldg(&b[lane]), 0.0f);
        unsigned gbase = (unsigned)__ldg(&batch[node]) * FDIM;
        atomicMax(&g_pool[gbase + lane], __float_as_uint(acc0));
        if (hi) {
            acc1 = fmaxf(acc1 + __ldg(&b[32 + lane]), 0.0f);
            atomicMax(&g_pool[gbase + 32 + lane], __float_as_uint(acc1));
        }
    } else {
        out[(size_t)node * FDIM + lane] = acc0;
        if (hi) out[(size_t)node * FDIM + 32 + lane] = acc1;
    }
}

// ---------------- GEMM v2: thread-per-node, broadcast W, packed f32x2 FMA ------
// out[n,:] = (relu)(in[n,:] @ W + b)
template <int FIN, int FOUT, bool RELU>
__global__ __launch_bounds__(256) void gemm2_k(const float* __restrict__ in,
                                               const float* __restrict__ W,
                                               const float* __restrict__ b,
                                               float* __restrict__ out) {
    __shared__ __align__(16) float sW[FIN * FOUT];
    __shared__ float sB[FOUT];
    for (int i = threadIdx.x; i < FIN * FOUT; i += 256) sW[i] = W[i];
    for (int i = threadIdx.x; i < FOUT; i += 256) sB[i] = b ? b[i] : 0.0f;
    __syncthreads();

    const int node = blockIdx.x * 256 + threadIdx.x;
    if (node >= NN) return;

    constexpr int C2 = FOUT / 2;
    unsigned long long acc[C2];
#pragma unroll
    for (int c2 = 0; c2 < C2; c2++) {
        float lo = sB[2 * c2], hi = sB[2 * c2 + 1];
        asm("mov.b64 %0, {%1, %2};" : "=l"(acc[c2]) : "f"(lo), "f"(hi));
    }

    const float4* __restrict__ in4 =
        reinterpret_cast<const float4*>(in + (size_t)node * FIN);
#pragma unroll 1
    for (int k4 = 0; k4 < FIN / 4; k4++) {
        float4 a = __ldg(&in4[k4]);
        float av[4] = {a.x, a.y, a.z, a.w};
#pragma unroll
        for (int kk = 0; kk < 4; kk++) {
            const int k = k4 * 4 + kk;
            unsigned long long ad;
            asm("mov.b64 %0, {%1, %1};" : "=l"(ad) : "f"(av[kk]));
            const ulonglong2* __restrict__ w4 =
                reinterpret_cast<const ulonglong2*>(sW + k * FOUT);
#pragma unroll
            for (int c2 = 0; c2 < C2; c2 += 2) {
                ulonglong2 wv = w4[c2 >> 1];
                asm("fma.rn.f32x2 %0, %1, %2, %0;" : "+l"(acc[c2]) : "l"(ad), "l"(wv.x));
                asm("fma.rn.f32x2 %0, %1, %2, %0;" : "+l"(acc[c2 + 1]) : "l"(ad), "l"(wv.y));
            }
        }
    }

    float* __restrict__ orow = out + (size_t)node * FOUT;
#pragma unroll
    for (int c2 = 0; c2 < C2; c2++) {
        float lo, hi;
        asm("mov.b64 {%0, %1}, %2;" : "=f"(lo), "=f"(hi) : "l"(acc[c2]));
        if (RELU) { lo = fmaxf(lo, 0.0f); hi = fmaxf(hi, 0.0f); }
        orow[2 * c2] = lo;
        orow[2 * c2 + 1] = hi;
    }
}

// ---------------- pooling init ----------------
__global__ void pool_init_k() {
    int i = blockIdx.x * blockDim.x + threadIdx.x;
    if (i < GG * FDIM) g_pool[i] = 0u;
}

// ---------------- heads ----------------
__global__ __launch_bounds__(128) void final_k(
        const float* __restrict__ feature,
        const float* __restrict__ Wg,  const float* __restrict__ bg,
        const float* __restrict__ Wf1, const float* __restrict__ bf1,
        const float* __restrict__ Wf2, const float* __restrict__ bf2,
        float* __restrict__ out) {
    constexpr int GPB = 8;
    __shared__ float sf[GPB][1024];
    __shared__ float red1[GPB][4], red2[GPB][4];
    const int g0 = blockIdx.x * GPB;
    const int t = threadIdx.x;  // 128

#pragma unroll
    for (int q = 0; q < GPB; q++)
        for (int k = t; k < FEATD; k += 128)
            sf[q][k] = feature[(size_t)(g0 + q) * FEATD + k];
    __syncthreads();

    float acc[GPB];
    const float bb = bf1[t];
#pragma unroll
    for (int q = 0; q < GPB; q++) acc[q] = bb;
    for (int k = 0; k < FEATD; k++) {
        float w = __ldg(&Wf1[k * 128 + t]);
#pragma unroll
        for (int q = 0; q < GPB; q++) acc[q] += sf[q][k] * w;
    }
    const float w2 = Wf2[t];
    const float wg = (t < FDIM) ? Wg[t] : 0.0f;
    const int lane = t & 31, wid = t >> 5;
#pragma unroll
    for (int q = 0; q < GPB; q++) {
        float s2 = fmaxf(acc[q], 0.0f) * w2;
        float s1 = (t < FDIM) ? __uint_as_float(g_pool[(g0 + q) * FDIM + t]) * wg : 0.0f;
#pragma unroll
        for (int o = 16; o; o >>= 1) {
            s1 += __shfl_down_sync(0xffffffffu, s1, o);
            s2 += __shfl_down_sync(0xffffffffu, s2, o);
        }
        if (lane == 0) { red1[q][wid] = s1; red2[q][wid] = s2; }
    }
    __syncthreads();
    if (t < GPB) {
        int q = t;
        float a = red1[q][0] + red1[q][1] + red1[q][2] + red1[q][3];
        float c = red2[q][0] + red2[q][1] + red2[q][2] + red2[q][3];
        out[g0 + q] = fmaxf(a + bg[0], 0.0f) + c + bf2[0];
    }
}

// ---------------- launch ----------------
extern "C" void kernel_launch(void* const* d_in, const int* in_sizes, int n_in,
                              void* d_out, int out_size) {
    const float* x       = (const float*)d_in[0];
    const int*   ei      = (const int*)d_in[1];
    const int*   batch   = (const int*)d_in[2];
    const float* feature = (const float*)d_in[3];
    const float* W1 = (const float*)d_in[4];
    const float* b1 = (const float*)d_in[5];
    const float* W2 = (const float*)d_in[6];
    const float* b2 = (const float*)d_in[7];
    const float* W3 = (const float*)d_in[8];
    const float* b3 = (const float*)d_in[9];
    const float* Wg = (const float*)d_in[10];
    const float* bg = (const float*)d_in[11];
    const float* Wf1 = (const float*)d_in[12];
    const float* bf1 = (const float*)d_in[13];
    const float* Wf2 = (const float*)d_in[14];
    const float* bf2 = (const float*)d_in[15];
    float* out = (float*)d_out;

    const int* src = ei;        // edge_index[0]
    const int* dst = ei + EE;   // edge_index[1]

    void *pA, *pB, *pT;
    cudaGetSymbolAddress(&pA, g_bufA);
    cudaGetSymbolAddress(&pB, g_bufB);
    cudaGetSymbolAddress(&pT, g_tmp);
    float* bufA = (float*)pA;
    float* bufB = (float*)pB;
    float* tmp  = (float*)pT;

    const int AGG_GRID  = (NN + 3) / 4;
    const int GEMM_GRID = (NN + 255) / 256;

    // CSR build (reused by all 3 layers)
    hist_init_k<<<(NN + 255) / 256, 256>>>();
    hist_k<<<(EE + 255) / 256, 256>>>(dst);
    scan1_k<<<NB_SCAN, 1024>>>();
    scan2_k<<<1, 128>>>();
    scan3_k<<<(NN + 255) / 256, 256>>>();
    bin_k<<<(EE + 255) / 256, 256>>>(src, dst);
    pool_init_k<<<(GG * FDIM + 255) / 256, 256>>>();

    // layer 1 (aggregate-first): tmp = A_norm @ x ; bufA = relu(tmp@W1+b1)
    agg44_k<false><<<AGG_GRID, 128>>>(x, nullptr, tmp, nullptr);
    gemm2_k<44, 44, true><<<GEMM_GRID, 256>>>(tmp, W1, b1, bufA);

    // layer 2 (aggregate-first): tmp = A_norm @ bufA ; bufB = relu(tmp@W2+b2)
    agg44_k<false><<<AGG_GRID, 128>>>(bufA, nullptr, tmp, nullptr);
    gemm2_k<44, 88, true><<<GEMM_GRID, 256>>>(tmp, W2, b2, bufB);

    // layer 3 (transform-first): tmp = bufB@W3 ; pool(relu(A_norm@tmp + b3))
    gemm2_k<88, 44, false><<<GEMM_GRID, 256>>>(bufB, W3, nullptr, tmp);
    agg44_k<true><<<AGG_GRID, 128>>>(tmp, b3, nullptr, batch);

    // heads
    final_k<<<GG / 8, 128>>>(feature, Wg, bg, Wf1, bf1, Wf2, bf2, out);
}

// round 7
// speedup vs baseline: 2.0767x; 1.0231x over previous
#include <cuda_runtime.h>

#define NN 100000
#define EE 1000000
#define GG 1024
#define FDIM 44
#define FEATD 1019

// ---------------- static scratch ----------------
__device__ int      g_cnt[NN];
__device__ int      g_off[NN];
__device__ int      g_cur[NN];
__device__ int      g_alloc;
__device__ float    g_dinv[NN];
__device__ float2   g_csr[EE];
__device__ __align__(16) float g_bufA[(size_t)NN * FDIM];
__device__ __align__(16) float g_bufB[(size_t)NN * 2 * FDIM];
__device__ __align__(16) float g_tmp[(size_t)NN * FDIM];
__device__ unsigned g_pool[GG * FDIM];

// ---------------- histogram ----------------
__global__ void hist_k(const int* __restrict__ dst) {
    int e = blockIdx.x * blockDim.x + threadIdx.x;
    if (e < EE) atomicAdd(&g_cnt[dst[e]], 1);
}

// ---------------- bump allocation of CSR rows (order-free, warp-aggregated) ----
__global__ void alloc_k() {
    int i = blockIdx.x * blockDim.x + threadIdx.x;
    int lane = threadIdx.x & 31;
    int c = (i < NN) ? g_cnt[i] : 0;
    // inclusive warp scan of c
    int s = c;
#pragma unroll
    for (int o = 1; o < 32; o <<= 1) {
        int t = __shfl_up_sync(0xffffffffu, s, o);
        if (lane >= o) s += t;
    }
    int base = 0;
    if (lane == 31) base = atomicAdd(&g_alloc, s);   // s at lane31 = warp total
    base = __shfl_sync(0xffffffffu, base, 31);
    int off = base + s - c;                          // exclusive offset
    if (i < NN) {
        g_off[i] = off;
        g_cur[i] = off;                              // cursor starts at row base
        g_dinv[i] = rsqrtf((float)c + 1.0f);         // +1 self loop
    }
}

// ---------------- edge binning ----------------
__global__ void bin_k(const int* __restrict__ src, const int* __restrict__ dst) {
    int e = blockIdx.x * blockDim.x + threadIdx.x;
    if (e >= EE) return;
    int s = __ldg(&src[e]);
    int d = __ldg(&dst[e]);
    int pos = atomicAdd(&g_cur[d], 1);
    g_csr[pos] = make_float2(__int_as_float(s), g_dinv[s] * g_dinv[d]);
}

// ---------------- warp-per-node aggregation over 44 features ----------------
template <bool POOL>
__global__ __launch_bounds__(128) void agg44_k(const float* __restrict__ in,
                                               const float* __restrict__ b,
                                               float* __restrict__ out,
                                               const int* __restrict__ batch) {
    int node = blockIdx.x * 4 + (threadIdx.x >> 5);
    if (node >= NN) return;
    const int lane = threadIdx.x & 31;
    const bool hi = lane < (FDIM - 32);

    const float* __restrict__ row = in + (size_t)node * FDIM;
    float di = g_dinv[node];
    float sc = di * di;
    float acc0 = __ldg(&row[lane]) * sc;
    float acc1 = hi ? __ldg(&row[32 + lane]) * sc : 0.0f;

    const int n = g_cnt[node];
    const float2* __restrict__ csr = g_csr + g_off[node];

    int j = 0;
    for (; j + 4 <= n; j += 4) {
        float2 c0 = __ldg(&csr[j + 0]);
        float2 c1 = __ldg(&csr[j + 1]);
        float2 c2 = __ldg(&csr[j + 2]);
        float2 c3 = __ldg(&csr[j + 3]);
        const float* r0 = in + (size_t)__float_as_int(c0.x) * FDIM;
        const float* r1 = in + (size_t)__float_as_int(c1.x) * FDIM;
        const float* r2 = in + (size_t)__float_as_int(c2.x) * FDIM;
        const float* r3 = in + (size_t)__float_as_int(c3.x) * FDIM;
        float v00 = __ldg(&r0[lane]);
        float v10 = __ldg(&r1[lane]);
        float v20 = __ldg(&r2[lane]);
        float v30 = __ldg(&r3[lane]);
        float v01 = hi ? __ldg(&r0[32 + lane]) : 0.0f;
        float v11 = hi ? __ldg(&r1[32 + lane]) : 0.0f;
        float v21 = hi ? __ldg(&r2[32 + lane]) : 0.0f;
        float v31 = hi ? __ldg(&r3[32 + lane]) : 0.0f;
        acc0 += v00 * c0.y + v10 * c1.y + v20 * c2.y + v30 * c3.y;
        acc1 += v01 * c0.y + v11 * c1.y + v21 * c2.y + v31 * c3.y;
    }
    for (; j < n; j++) {
        float2 c = __ldg(&csr[j]);
        const float* r = in + (size_t)__float_as_int(c.x) * FDIM;
        acc0 += __ldg(&r[lane]) * c.y;
        if (hi) acc1 += __ldg(&r[32 + lane]) * c.y;
    }

    if (POOL) {
        acc0 = fmaxf(acc0 + __ldg(&b[lane]), 0.0f);
        unsigned gbase = (unsigned)__ldg(&batch[node]) * FDIM;
        atomicMax(&g_pool[gbase + lane], __float_as_uint(acc0));
        if (hi) {
            acc1 = fmaxf(acc1 + __ldg(&b[32 + lane]), 0.0f);
            atomicMax(&g_pool[gbase + 32 + lane], __float_as_uint(acc1));
        }
    } else {
        out[(size_t)node * FDIM + lane] = acc0;
        if (hi) out[(size_t)node * FDIM + 32 + lane] = acc1;
    }
}

// ---------------- GEMM: thread-per-node, COLS outputs per thread, f32x2 FMA ----
// out[n, col0:col0+COLS] = (relu)(in[n,:] @ W[:, col0:col0+COLS] + b)
template <int FIN, int FOUT, int COLS, bool RELU>
__global__ __launch_bounds__(256) void gemm2_k(const float* __restrict__ in,
                                               const float* __restrict__ W,
                                               const float* __restrict__ b,
                                               float* __restrict__ out) {
    __shared__ __align__(16) float sW[FIN * COLS];
    __shared__ float sB[COLS];
    const int col0 = blockIdx.y * COLS;
    for (int i = threadIdx.x; i < FIN * COLS; i += 256) {
        int k = i / COLS, c = i - k * COLS;
        sW[i] = W[k * FOUT + col0 + c];
    }
    for (int i = threadIdx.x; i < COLS; i += 256) sB[i] = b ? b[col0 + i] : 0.0f;
    __syncthreads();

    const int node = blockIdx.x * 256 + threadIdx.x;
    if (node >= NN) return;

    constexpr int C2 = COLS / 2;
    unsigned long long acc[C2];
#pragma unroll
    for (int c2 = 0; c2 < C2; c2++) {
        float lo = sB[2 * c2], hi = sB[2 * c2 + 1];
        asm("mov.b64 %0, {%1, %2};" : "=l"(acc[c2]) : "f"(lo), "f"(hi));
    }

    const float4* __restrict__ in4 =
        reinterpret_cast<const float4*>(in + (size_t)node * FIN);
#pragma unroll 1
    for (int k4 = 0; k4 < FIN / 4; k4++) {
        float4 a = __ldg(&in4[k4]);
        float av[4] = {a.x, a.y, a.z, a.w};
#pragma unroll
        for (int kk = 0; kk < 4; kk++) {
            const int k = k4 * 4 + kk;
            unsigned long long ad;
            asm("mov.b64 %0, {%1, %1};" : "=l"(ad) : "f"(av[kk]));
            const ulonglong2* __restrict__ w4 =
                reinterpret_cast<const ulonglong2*>(sW + k * COLS);
#pragma unroll
            for (int c2 = 0; c2 < C2; c2 += 2) {
                ulonglong2 wv = w4[c2 >> 1];
                asm("fma.rn.f32x2 %0, %1, %2, %0;" : "+l"(acc[c2]) : "l"(ad), "l"(wv.x));
                asm("fma.rn.f32x2 %0, %1, %2, %0;" : "+l"(acc[c2 + 1]) : "l"(ad), "l"(wv.y));
            }
        }
    }

    float* __restrict__ orow = out + (size_t)node * FOUT + col0;
#pragma unroll
    for (int c2 = 0; c2 < C2; c2++) {
        float lo, hi;
        asm("mov.b64 {%0, %1}, %2;" : "=f"(lo), "=f"(hi) : "l"(acc[c2]));
        if (RELU) { lo = fmaxf(lo, 0.0f); hi = fmaxf(hi, 0.0f); }
        orow[2 * c2] = lo;
        orow[2 * c2 + 1] = hi;
    }
}

// ---------------- heads ----------------
__global__ __launch_bounds__(128) void final_k(
        const float* __restrict__ feature,
        const float* __restrict__ Wg,  const float* __restrict__ bg,
        const float* __restrict__ Wf1, const float* __restrict__ bf1,
        const float* __restrict__ Wf2, const float* __restrict__ bf2,
        float* __restrict__ out) {
    constexpr int GPB = 8;
    __shared__ float sf[GPB][1024];
    __shared__ float red1[GPB][4], red2[GPB][4];
    const int g0 = blockIdx.x * GPB;
    const int t = threadIdx.x;  // 128

#pragma unroll
    for (int q = 0; q < GPB; q++)
        for (int k = t; k < FEATD; k += 128)
            sf[q][k] = feature[(size_t)(g0 + q) * FEATD + k];
    __syncthreads();

    float acc[GPB];
    const float bb = bf1[t];
#pragma unroll
    for (int q = 0; q < GPB; q++) acc[q] = bb;
    for (int k = 0; k < FEATD; k++) {
        float w = __ldg(&Wf1[k * 128 + t]);
#pragma unroll
        for (int q = 0; q < GPB; q++) acc[q] += sf[q][k] * w;
    }
    const float w2 = Wf2[t];
    const float wg = (t < FDIM) ? Wg[t] : 0.0f;
    const int lane = t & 31, wid = t >> 5;
#pragma unroll
    for (int q = 0; q < GPB; q++) {
        float s2 = fmaxf(acc[q], 0.0f) * w2;
        float s1 = (t < FDIM) ? __uint_as_float(g_pool[(g0 + q) * FDIM + t]) * wg : 0.0f;
#pragma unroll
        for (int o = 16; o; o >>= 1) {
            s1 += __shfl_down_sync(0xffffffffu, s1, o);
            s2 += __shfl_down_sync(0xffffffffu, s2, o);
        }
        if (lane == 0) { red1[q][wid] = s1; red2[q][wid] = s2; }
    }
    __syncthreads();
    if (t < GPB) {
        int q = t;
        float a = red1[q][0] + red1[q][1] + red1[q][2] + red1[q][3];
        float c = red2[q][0] + red2[q][1] + red2[q][2] + red2[q][3];
        out[g0 + q] = fmaxf(a + bg[0], 0.0f) + c + bf2[0];
    }
}

// ---------------- launch ----------------
extern "C" void kernel_launch(void* const* d_in, const int* in_sizes, int n_in,
                              void* d_out, int out_size) {
    const float* x       = (const float*)d_in[0];
    const int*   ei      = (const int*)d_in[1];
    const int*   batch   = (const int*)d_in[2];
    const float* feature = (const float*)d_in[3];
    const float* W1 = (const float*)d_in[4];
    const float* b1 = (const float*)d_in[5];
    const float* W2 = (const float*)d_in[6];
    const float* b2 = (const float*)d_in[7];
    const float* W3 = (const float*)d_in[8];
    const float* b3 = (const float*)d_in[9];
    const float* Wg = (const float*)d_in[10];
    const float* bg = (const float*)d_in[11];
    const float* Wf1 = (const float*)d_in[12];
    const float* bf1 = (const float*)d_in[13];
    const float* Wf2 = (const float*)d_in[14];
    const float* bf2 = (const float*)d_in[15];
    float* out = (float*)d_out;

    const int* src = ei;        // edge_index[0]
    const int* dst = ei + EE;   // edge_index[1]

    void *pA, *pB, *pT, *pCnt, *pPool, *pAlloc;
    cudaGetSymbolAddress(&pA, g_bufA);
    cudaGetSymbolAddress(&pB, g_bufB);
    cudaGetSymbolAddress(&pT, g_tmp);
    cudaGetSymbolAddress(&pCnt, g_cnt);
    cudaGetSymbolAddress(&pPool, g_pool);
    cudaGetSymbolAddress(&pAlloc, g_alloc);
    float* bufA = (float*)pA;
    float* bufB = (float*)pB;
    float* tmp  = (float*)pT;

    const int AGG_GRID  = (NN + 3) / 4;
    const int GEMM_GRID = (NN + 255) / 256;

    // zero-fill via memset nodes (not kernel launches)
    cudaMemsetAsync(pCnt, 0, NN * sizeof(int));
    cudaMemsetAsync(pPool, 0, GG * FDIM * sizeof(unsigned));
    cudaMemsetAsync(pAlloc, 0, sizeof(int));

    // CSR build (bump allocation; no scan)
    hist_k<<<(EE + 255) / 256, 256>>>(dst);                      // launch 1
    alloc_k<<<(NN + 255) / 256, 256>>>();                        // launch 2
    bin_k<<<(EE + 255) / 256, 256>>>(src, dst);                  // launch 3

    // layer 1 (aggregate-first): tmp = A_norm @ x ; bufA = relu(tmp@W1+b1)
    agg44_k<false><<<AGG_GRID, 128>>>(x, nullptr, tmp, nullptr); // launch 4 (profiled)
    gemm2_k<44, 44, 44, true><<<dim3(GEMM_GRID, 1), 256>>>(tmp, W1, b1, bufA);

    // layer 2 (aggregate-first): tmp = A_norm @ bufA ; bufB = relu(tmp@W2+b2)
    agg44_k<false><<<AGG_GRID, 128>>>(bufA, nullptr, tmp, nullptr);
    gemm2_k<44, 88, 44, true><<<dim3(GEMM_GRID, 2), 256>>>(tmp, W2, b2, bufB);

    // layer 3 (transform-first): tmp = bufB@W3 ; pool(relu(A_norm@tmp + b3))
    gemm2_k<88, 44, 44, false><<<dim3(GEMM_GRID, 1), 256>>>(bufB, W3, nullptr, tmp);
    agg44_k<true><<<AGG_GRID, 128>>>(tmp, b3, nullptr, batch);

    // heads
    final_k<<<GG / 8, 128>>>(feature, Wg, bg, Wf1, bf1, Wf2, bf2, out);
}

// round 9
// speedup vs baseline: 2.0890x; 1.0059x over previous
#include <cuda_runtime.h>

#define NN 100000
#define EE 1000000
#define GG 1024
#define FDIM 44
#define FEATD 1019

// ---------------- static scratch ----------------
__device__ int      g_cnt[NN];
__device__ int      g_off[NN];
__device__ int      g_cur[NN];
__device__ int      g_alloc;
__device__ float    g_dinv[NN];
__device__ __align__(16) float2 g_csr[EE];   // {src*22 (int bits), norm}
__device__ __align__(16) float g_bufA[(size_t)NN * FDIM];
__device__ __align__(16) float g_bufB[(size_t)NN * 2 * FDIM];
__device__ __align__(16) float g_tmp[(size_t)NN * FDIM];
__device__ unsigned g_pool[GG * FDIM];

// ---------------- histogram ----------------
__global__ void hist_k(const int* __restrict__ dst) {
    int e = blockIdx.x * blockDim.x + threadIdx.x;
    if (e < EE) atomicAdd(&g_cnt[dst[e]], 1);
}

// ---------------- bump allocation of CSR rows (order-free, warp-aggregated) ----
__global__ void alloc_k() {
    int i = blockIdx.x * blockDim.x + threadIdx.x;
    int lane = threadIdx.x & 31;
    int c = (i < NN) ? g_cnt[i] : 0;
    int s = c;
#pragma unroll
    for (int o = 1; o < 32; o <<= 1) {
        int t = __shfl_up_sync(0xffffffffu, s, o);
        if (lane >= o) s += t;
    }
    int base = 0;
    if (lane == 31) base = atomicAdd(&g_alloc, s);
    base = __shfl_sync(0xffffffffu, base, 31);
    int off = base + s - c;
    if (i < NN) {
        g_off[i] = off;
        g_cur[i] = off;
        g_dinv[i] = rsqrtf((float)c + 1.0f);
    }
}

// ---------------- edge binning (store pre-scaled float2 offset) ----------------
__global__ void bin_k(const int* __restrict__ src, const int* __restrict__ dst) {
    int e = blockIdx.x * blockDim.x + threadIdx.x;
    if (e >= EE) return;
    int s = __ldg(&src[e]);
    int d = __ldg(&dst[e]);
    int pos = atomicAdd(&g_cur[d], 1);
    g_csr[pos] = make_float2(__int_as_float(s * (FDIM / 2)), g_dinv[s] * g_dinv[d]);
}

// ---------------- warp-per-node aggregation, float2 per lane ----------------
// lane < 22 owns features [2*lane, 2*lane+1]
template <bool POOL>
__global__ __launch_bounds__(256) void agg44_k(const float* __restrict__ in,
                                               const float* __restrict__ b,
                                               float* __restrict__ out,
                                               const int* __restrict__ batch) {
    int node = blockIdx.x * 8 + (threadIdx.x >> 5);
    if (node >= NN) return;
    const int lane = threadIdx.x & 31;
    const bool act = lane < (FDIM / 2);

    const float2* __restrict__ f2base = reinterpret_cast<const float2*>(in) + lane;
    const int self = node * (FDIM / 2);

    float di = g_dinv[node];
    float sc = di * di;
    float2 acc = make_float2(0.0f, 0.0f);
    if (act) {
        float2 v = __ldg(&f2base[self]);
        acc.x = v.x * sc;
        acc.y = v.y * sc;
    }

    const int n = g_cnt[node];
    const float2* __restrict__ csr = g_csr + g_off[node];

    int j = 0;
    for (; j + 4 <= n; j += 4) {
        float2 c0 = __ldg(&csr[j + 0]);
        float2 c1 = __ldg(&csr[j + 1]);
        float2 c2 = __ldg(&csr[j + 2]);
        float2 c3 = __ldg(&csr[j + 3]);
        if (act) {
            float2 v0 = __ldg(&f2base[__float_as_int(c0.x)]);
            float2 v1 = __ldg(&f2base[__float_as_int(c1.x)]);
            float2 v2 = __ldg(&f2base[__float_as_int(c2.x)]);
            float2 v3 = __ldg(&f2base[__float_as_int(c3.x)]);
            acc.x += v0.x * c0.y + v1.x * c1.y + v2.x * c2.y + v3.x * c3.y;
            acc.y += v0.y * c0.y + v1.y * c1.y + v2.y * c2.y + v3.y * c3.y;
        }
    }
    for (; j < n; j++) {
        float2 c = __ldg(&csr[j]);
        if (act) {
            float2 v = __ldg(&f2base[__float_as_int(c.x)]);
            acc.x += v.x * c.y;
            acc.y += v.y * c.y;
        }
    }

    if (act) {
        if (POOL) {
            float2 bb = __ldg(&reinterpret_cast<const float2*>(b)[lane]);
            acc.x = fmaxf(acc.x + bb.x, 0.0f);
            acc.y = fmaxf(acc.y + bb.y, 0.0f);
            unsigned gbase = (unsigned)__ldg(&batch[node]) * FDIM + 2 * lane;
            atomicMax(&g_pool[gbase + 0], __float_as_uint(acc.x));
            atomicMax(&g_pool[gbase + 1], __float_as_uint(acc.y));
        } else {
            reinterpret_cast<float2*>(out)[self + lane] = acc;
        }
    }
}

// ---------------- GEMM: thread-per-node, COLS outputs per thread, f32x2 FMA ----
template <int FIN, int FOUT, int COLS, bool RELU>
__global__ __launch_bounds__(256) void gemm2_k(const float* __restrict__ in,
                                               const float* __restrict__ W,
                                               const float* __restrict__ b,
                                               float* __restrict__ out) {
    __shared__ __align__(16) float sW[FIN * COLS];
    __shared__ float sB[COLS];
    const int col0 = blockIdx.y * COLS;
    for (int i = threadIdx.x; i < FIN * COLS; i += 256) {
        int k = i / COLS, c = i - k * COLS;
        sW[i] = W[k * FOUT + col0 + c];
    }
    for (int i = threadIdx.x; i < COLS; i += 256) sB[i] = b ? b[col0 + i] : 0.0f;
    __syncthreads();

    const int node = blockIdx.x * 256 + threadIdx.x;
    if (node >= NN) return;

    constexpr int C2 = COLS / 2;
    unsigned long long acc[C2];
#pragma unroll
    for (int c2 = 0; c2 < C2; c2++) {
        float lo = sB[2 * c2], hi = sB[2 * c2 + 1];
        asm("mov.b64 %0, {%1, %2};" : "=l"(acc[c2]) : "f"(lo), "f"(hi));
    }

    const float4* __restrict__ in4 =
        reinterpret_cast<const float4*>(in + (size_t)node * FIN);
#pragma unroll 1
    for (int k4 = 0; k4 < FIN / 4; k4++) {
        float4 a = __ldg(&in4[k4]);
        float av[4] = {a.x, a.y, a.z, a.w};
#pragma unroll
        for (int kk = 0; kk < 4; kk++) {
            const int k = k4 * 4 + kk;
            unsigned long long ad;
            asm("mov.b64 %0, {%1, %1};" : "=l"(ad) : "f"(av[kk]));
            const ulonglong2* __restrict__ w4 =
                reinterpret_cast<const ulonglong2*>(sW + k * COLS);
#pragma unroll
            for (int c2 = 0; c2 < C2; c2 += 2) {
                ulonglong2 wv = w4[c2 >> 1];
                asm("fma.rn.f32x2 %0, %1, %2, %0;" : "+l"(acc[c2]) : "l"(ad), "l"(wv.x));
                asm("fma.rn.f32x2 %0, %1, %2, %0;" : "+l"(acc[c2 + 1]) : "l"(ad), "l"(wv.y));
            }
        }
    }

    float* __restrict__ orow = out + (size_t)node * FOUT + col0;
#pragma unroll
    for (int c2 = 0; c2 < C2; c2++) {
        float lo, hi;
        asm("mov.b64 {%0, %1}, %2;" : "=f"(lo), "=f"(hi) : "l"(acc[c2]));
        if (RELU) { lo = fmaxf(lo, 0.0f); hi = fmaxf(hi, 0.0f); }
        orow[2 * c2] = lo;
        orow[2 * c2 + 1] = hi;
    }
}

// ---------------- heads (split-K over 2 thread halves) ----------------
__global__ __launch_bounds__(256) void final_k(
        const float* __restrict__ feature,
        const float* __restrict__ Wg,  const float* __restrict__ bg,
        const float* __restrict__ Wf1, const float* __restrict__ bf1,
        const float* __restrict__ Wf2, const float* __restrict__ bf2,
        float* __restrict__ out) {
    constexpr int GPB = 8;
    constexpr int KSPLIT = 512;
    __shared__ float sf[GPB][1024];
    __shared__ float sacc[GPB][128];
    __shared__ float red1[GPB][4], red2[GPB][4];
    const int g0 = blockIdx.x * GPB;
    const int t = threadIdx.x;   // 256
    const int h = t & 127;       // hidden unit
    const int half = t >> 7;     // k-range half

#pragma unroll
    for (int q = 0; q < GPB; q++)
        for (int k = t; k < FEATD; k += 256)
            sf[q][k] = feature[(size_t)(g0 + q) * FEATD + k];
    __syncthreads();

    float acc[GPB];
    const float bb = (half == 0) ? bf1[h] : 0.0f;
#pragma unroll
    for (int q = 0; q < GPB; q++) acc[q] = bb;
    const int k0 = half ? KSPLIT : 0;
    const int k1 = half ? FEATD : KSPLIT;
    for (int k = k0; k < k1; k++) {
        float w = __ldg(&Wf1[k * 128 + h]);
#pragma unroll
        for (int q = 0; q < GPB; q++) acc[q] += sf[q][k] * w;
    }
    if (half == 1) {
#pragma unroll
        for (int q = 0; q < GPB; q++) sacc[q][h] = acc[q];
    }
    __syncthreads();

    if (half == 0) {
        const float w2 = Wf2[h];
        const float wg = (h < FDIM) ? Wg[h] : 0.0f;
        const int lane = h & 31, wid = h >> 5;
#pragma unroll
        for (int q = 0; q < GPB; q++) {
            float hidden = acc[q] + sacc[q][h];
            float s2 = fmaxf(hidden, 0.0f) * w2;
            float s1 = (h < FDIM) ? __uint_as_float(g_pool[(g0 + q) * FDIM + h]) * wg : 0.0f;
#pragma unroll
            for (int o = 16; o; o >>= 1) {
                s1 += __shfl_down_sync(0xffffffffu, s1, o);
                s2 += __shfl_down_sync(0xffffffffu, s2, o);
            }
            if (lane == 0) { red1[q][wid] = s1; red2[q][wid] = s2; }
        }
    }
    __syncthreads();
    if (t < GPB) {
        int q = t;
        float a = red1[q][0] + red1[q][1] + red1[q][2] + red1[q][3];
        float c = red2[q][0] + red2[q][1] + red2[q][2] + red2[q][3];
        out[g0 + q] = fmaxf(a + bg[0], 0.0f) + c + bf2[0];
    }
}

// ---------------- launch ----------------
extern "C" void kernel_launch(void* const* d_in, const int* in_sizes, int n_in,
                              void* d_out, int out_size) {
    const float* x       = (const float*)d_in[0];
    const int*   ei      = (const int*)d_in[1];
    const int*   batch   = (const int*)d_in[2];
    const float* feature = (const float*)d_in[3];
    const float* W1 = (const float*)d_in[4];
    const float* b1 = (const float*)d_in[5];
    const float* W2 = (const float*)d_in[6];
    const float* b2 = (const float*)d_in[7];
    const float* W3 = (const float*)d_in[8];
    const float* b3 = (const float*)d_in[9];
    const float* Wg = (const float*)d_in[10];
    const float* bg = (const float*)d_in[11];
    const float* Wf1 = (const float*)d_in[12];
    const float* bf1 = (const float*)d_in[13];
    const float* Wf2 = (const float*)d_in[14];
    const float* bf2 = (const float*)d_in[15];
    float* out = (float*)d_out;

    const int* src = ei;        // edge_index[0]
    const int* dst = ei + EE;   // edge_index[1]

    void *pA, *pB, *pT, *pCnt, *pPool, *pAlloc;
    cudaGetSymbolAddress(&pA, g_bufA);
    cudaGetSymbolAddress(&pB, g_bufB);
    cudaGetSymbolAddress(&pT, g_tmp);
    cudaGetSymbolAddress(&pCnt, g_cnt);
    cudaGetSymbolAddress(&pPool, g_pool);
    cudaGetSymbolAddress(&pAlloc, g_alloc);
    float* bufA = (float*)pA;
    float* bufB = (float*)pB;
    float* tmp  = (float*)pT;

    const int AGG_GRID  = (NN + 7) / 8;
    const int GEMM_GRID = (NN + 255) / 256;

    cudaMemsetAsync(pCnt, 0, NN * sizeof(int));
    cudaMemsetAsync(pPool, 0, GG * FDIM * sizeof(unsigned));
    cudaMemsetAsync(pAlloc, 0, sizeof(int));

    // CSR build
    hist_k<<<(EE + 255) / 256, 256>>>(dst);
    alloc_k<<<(NN + 255) / 256, 256>>>();
    bin_k<<<(EE + 255) / 256, 256>>>(src, dst);

    // layer 1 (aggregate-first): tmp = A_norm @ x ; bufA = relu(tmp@W1+b1)
    agg44_k<false><<<AGG_GRID, 256>>>(x, nullptr, tmp, nullptr);
    gemm2_k<44, 44, 44, true><<<dim3(GEMM_GRID, 1), 256>>>(tmp, W1, b1, bufA);

    // layer 2 (aggregate-first): tmp = A_norm @ bufA ; bufB = relu(tmp@W2+b2)
    agg44_k<false><<<AGG_GRID, 256>>>(bufA, nullptr, tmp, nullptr);   // profiled (6th)
    gemm2_k<44, 88, 44, true><<<dim3(GEMM_GRID, 2), 256>>>(tmp, W2, b2, bufB);

    // layer 3 (transform-first): tmp = bufB@W3 ; pool(relu(A_norm@tmp + b3))
    gemm2_k<88, 44, 44, false><<<dim3(GEMM_GRID, 1), 256>>>(bufB, W3, nullptr, tmp);
    agg44_k<true><<<AGG_GRID, 256>>>(tmp, b3, nullptr, batch);

    // heads
    final_k<<<GG / 8, 256>>>(feature, Wg, bg, Wf1, bf1, Wf2, bf2, out);
}

// round 10
// speedup vs baseline: 2.2415x; 1.0730x over previous
#include <cuda_runtime.h>

#define NN 100000
#define EE 1000000
#define GG 1024
#define FDIM 44
#define FEATD 1019

// ---------------- static scratch ----------------
__device__ int      g_cnt[NN];
__device__ int      g_off[NN];
__device__ int      g_cur[NN];
__device__ int      g_alloc;
__device__ float    g_dinv[NN];
__device__ __align__(16) float2 g_csr[EE + NN];  // {src*44 (int bits), norm}; rows even-aligned
__device__ __align__(16) float g_bufA[(size_t)NN * FDIM];
__device__ __align__(16) float g_bufB[(size_t)NN * 2 * FDIM];
__device__ __align__(16) float g_tmp[(size_t)NN * FDIM];
__device__ unsigned g_pool[GG * FDIM];

// ---------------- histogram ----------------
__global__ void hist_k(const int* __restrict__ dst) {
    int e = blockIdx.x * blockDim.x + threadIdx.x;
    if (e < EE) atomicAdd(&g_cnt[dst[e]], 1);
}

// ---------------- bump allocation of CSR rows (even-aligned starts) ----------
__global__ void alloc_k() {
    int i = blockIdx.x * blockDim.x + threadIdx.x;
    int lane = threadIdx.x & 31;
    int c = (i < NN) ? g_cnt[i] : 0;
    int cp = (c + 1) & ~1;          // pad row length to even => starts stay even
    int s = cp;
#pragma unroll
    for (int o = 1; o < 32; o <<= 1) {
        int t = __shfl_up_sync(0xffffffffu, s, o);
        if (lane >= o) s += t;
    }
    int base = 0;
    if (lane == 31) base = atomicAdd(&g_alloc, s);
    base = __shfl_sync(0xffffffffu, base, 31);
    int off = base + s - cp;
    if (i < NN) {
        g_off[i] = off;
        g_cur[i] = off;
        g_dinv[i] = rsqrtf((float)c + 1.0f);
    }
}

// ---------------- edge binning (store pre-scaled float offset src*44) --------
__global__ void bin_k(const int* __restrict__ src, const int* __restrict__ dst) {
    int e = blockIdx.x * blockDim.x + threadIdx.x;
    if (e >= EE) return;
    int s = __ldg(&src[e]);
    int d = __ldg(&dst[e]);
    int pos = atomicAdd(&g_cur[d], 1);
    g_csr[pos] = make_float2(__int_as_float(s * FDIM), g_dinv[s] * g_dinv[d]);
}

// ---------------- warp-per-node aggregation (two chunks: lane, 32+lane) ------
template <bool POOL>
__global__ __launch_bounds__(128) void agg44_k(const float* __restrict__ in,
                                               const float* __restrict__ b,
                                               float* __restrict__ out,
                                               const int* __restrict__ batch) {
    int node = blockIdx.x * 4 + (threadIdx.x >> 5);
    if (node >= NN) return;
    const int lane = threadIdx.x & 31;
    const bool hi = lane < (FDIM - 32);   // 12 lanes own chunk 1

    const float* __restrict__ base0 = in + lane;
    const int selfoff = node * FDIM;

    float di = g_dinv[node];
    float sc = di * di;
    float acc0 = __ldg(&base0[selfoff]) * sc;
    float acc1 = hi ? __ldg(&base0[selfoff + 32]) * sc : 0.0f;

    const int n = g_cnt[node];
    const float2* __restrict__ csr = g_csr + g_off[node];   // even-aligned

    int j = 0;
    for (; j + 4 <= n; j += 4) {
        float4 p0 = __ldg(reinterpret_cast<const float4*>(csr + j));
        float4 p1 = __ldg(reinterpret_cast<const float4*>(csr + j + 2));
        int o0 = __float_as_int(p0.x);
        int o1 = __float_as_int(p0.z);
        int o2 = __float_as_int(p1.x);
        int o3 = __float_as_int(p1.z);
        float v00 = __ldg(&base0[o0]);
        float v10 = __ldg(&base0[o1]);
        float v20 = __ldg(&base0[o2]);
        float v30 = __ldg(&base0[o3]);
        float v01 = hi ? __ldg(&base0[o0 + 32]) : 0.0f;
        float v11 = hi ? __ldg(&base0[o1 + 32]) : 0.0f;
        float v21 = hi ? __ldg(&base0[o2 + 32]) : 0.0f;
        float v31 = hi ? __ldg(&base0[o3 + 32]) : 0.0f;
        acc0 += v00 * p0.y + v10 * p0.w + v20 * p1.y + v30 * p1.w;
        acc1 += v01 * p0.y + v11 * p0.w + v21 * p1.y + v31 * p1.w;
    }
    for (; j < n; j++) {
        float2 c = __ldg(&csr[j]);
        int o = __float_as_int(c.x);
        acc0 += __ldg(&base0[o]) * c.y;
        if (hi) acc1 += __ldg(&base0[o + 32]) * c.y;
    }

    if (POOL) {
        acc0 = fmaxf(acc0 + __ldg(&b[lane]), 0.0f);
        unsigned gbase = (unsigned)__ldg(&batch[node]) * FDIM;
        atomicMax(&g_pool[gbase + lane], __float_as_uint(acc0));
        if (hi) {
            acc1 = fmaxf(acc1 + __ldg(&b[32 + lane]), 0.0f);
            atomicMax(&g_pool[gbase + 32 + lane], __float_as_uint(acc1));
        }
    } else {
        out[selfoff + lane] = acc0;
        if (hi) out[selfoff + 32 + lane] = acc1;
    }
}

// ---------------- GEMM: thread-per-node, COLS outputs per thread, f32x2 FMA ----
template <int FIN, int FOUT, int COLS, bool RELU>
__global__ __launch_bounds__(256) void gemm2_k(const float* __restrict__ in,
                                               const float* __restrict__ W,
                                               const float* __restrict__ b,
                                               float* __restrict__ out) {
    __shared__ __align__(16) float sW[FIN * COLS];
    __shared__ float sB[COLS];
    const int col0 = blockIdx.y * COLS;
    for (int i = threadIdx.x; i < FIN * COLS; i += 256) {
        int k = i / COLS, c = i - k * COLS;
        sW[i] = W[k * FOUT + col0 + c];
    }
    for (int i = threadIdx.x; i < COLS; i += 256) sB[i] = b ? b[col0 + i] : 0.0f;
    __syncthreads();

    const int node = blockIdx.x * 256 + threadIdx.x;
    if (node >= NN) return;

    constexpr int C2 = COLS / 2;
    unsigned long long acc[C2];
#pragma unroll
    for (int c2 = 0; c2 < C2; c2++) {
        float lo = sB[2 * c2], hi = sB[2 * c2 + 1];
        asm("mov.b64 %0, {%1, %2};" : "=l"(acc[c2]) : "f"(lo), "f"(hi));
    }

    const float4* __restrict__ in4 =
        reinterpret_cast<const float4*>(in + (size_t)node * FIN);
#pragma unroll 1
    for (int k4 = 0; k4 < FIN / 4; k4++) {
        float4 a = __ldg(&in4[k4]);
        float av[4] = {a.x, a.y, a.z, a.w};
#pragma unroll
        for (int kk = 0; kk < 4; kk++) {
            const int k = k4 * 4 + kk;
            unsigned long long ad;
            asm("mov.b64 %0, {%1, %1};" : "=l"(ad) : "f"(av[kk]));
            const ulonglong2* __restrict__ w4 =
                reinterpret_cast<const ulonglong2*>(sW + k * COLS);
#pragma unroll
            for (int c2 = 0; c2 < C2; c2 += 2) {
                ulonglong2 wv = w4[c2 >> 1];
                asm("fma.rn.f32x2 %0, %1, %2, %0;" : "+l"(acc[c2]) : "l"(ad), "l"(wv.x));
                asm("fma.rn.f32x2 %0, %1, %2, %0;" : "+l"(acc[c2 + 1]) : "l"(ad), "l"(wv.y));
            }
        }
    }

    float* __restrict__ orow = out + (size_t)node * FOUT + col0;
#pragma unroll
    for (int c2 = 0; c2 < C2; c2++) {
        float lo, hi;
        asm("mov.b64 {%0, %1}, %2;" : "=f"(lo), "=f"(hi) : "l"(acc[c2]));
        if (RELU) { lo = fmaxf(lo, 0.0f); hi = fmaxf(hi, 0.0f); }
        orow[2 * c2] = lo;
        orow[2 * c2 + 1] = hi;
    }
}

// ---------------- heads (split-K over 2 thread halves) ----------------
__global__ __launch_bounds__(256) void final_k(
        const float* __restrict__ feature,
        const float* __restrict__ Wg,  const float* __restrict__ bg,
        const float* __restrict__ Wf1, const float* __restrict__ bf1,
        const float* __restrict__ Wf2, const float* __restrict__ bf2,
        float* __restrict__ out) {
    constexpr int GPB = 8;
    constexpr int KSPLIT = 512;
    __shared__ float sf[GPB][1024];
    __shared__ float sacc[GPB][128];
    __shared__ float red1[GPB][4], red2[GPB][4];
    const int g0 = blockIdx.x * GPB;
    const int t = threadIdx.x;   // 256
    const int h = t & 127;
    const int half = t >> 7;

#pragma unroll
    for (int q = 0; q < GPB; q++)
        for (int k = t; k < FEATD; k += 256)
            sf[q][k] = feature[(size_t)(g0 + q) * FEATD + k];
    __syncthreads();

    float acc[GPB];
    const float bb = (half == 0) ? bf1[h] : 0.0f;
#pragma unroll
    for (int q = 0; q < GPB; q++) acc[q] = bb;
    const int k0 = half ? KSPLIT : 0;
    const int k1 = half ? FEATD : KSPLIT;
    for (int k = k0; k < k1; k++) {
        float w = __ldg(&Wf1[k * 128 + h]);
#pragma unroll
        for (int q = 0; q < GPB; q++) acc[q] += sf[q][k] * w;
    }
    if (half == 1) {
#pragma unroll
        for (int q = 0; q < GPB; q++) sacc[q][h] = acc[q];
    }
    __syncthreads();

    if (half == 0) {
        const float w2 = Wf2[h];
        const float wg = (h < FDIM) ? Wg[h] : 0.0f;
        const int lane = h & 31, wid = h >> 5;
#pragma unroll
        for (int q = 0; q < GPB; q++) {
            float hidden = acc[q] + sacc[q][h];
            float s2 = fmaxf(hidden, 0.0f) * w2;
            float s1 = (h < FDIM) ? __uint_as_float(g_pool[(g0 + q) * FDIM + h]) * wg : 0.0f;
#pragma unroll
            for (int o = 16; o; o >>= 1) {
                s1 += __shfl_down_sync(0xffffffffu, s1, o);
                s2 += __shfl_down_sync(0xffffffffu, s2, o);
            }
            if (lane == 0) { red1[q][wid] = s1; red2[q][wid] = s2; }
        }
    }
    __syncthreads();
    if (t < GPB) {
        int q = t;
        float a = red1[q][0] + red1[q][1] + red1[q][2] + red1[q][3];
        float c = red2[q][0] + red2[q][1] + red2[q][2] + red2[q][3];
        out[g0 + q] = fmaxf(a + bg[0], 0.0f) + c + bf2[0];
    }
}

// ---------------- launch ----------------
extern "C" void kernel_launch(void* const* d_in, const int* in_sizes, int n_in,
                              void* d_out, int out_size) {
    const float* x       = (const float*)d_in[0];
    const int*   ei      = (const int*)d_in[1];
    const int*   batch   = (const int*)d_in[2];
    const float* feature = (const float*)d_in[3];
    const float* W1 = (const float*)d_in[4];
    const float* b1 = (const float*)d_in[5];
    const float* W2 = (const float*)d_in[6];
    const float* b2 = (const float*)d_in[7];
    const float* W3 = (const float*)d_in[8];
    const float* b3 = (const float*)d_in[9];
    const float* Wg = (const float*)d_in[10];
    const float* bg = (const float*)d_in[11];
    const float* Wf1 = (const float*)d_in[12];
    const float* bf1 = (const float*)d_in[13];
    const float* Wf2 = (const float*)d_in[14];
    const float* bf2 = (const float*)d_in[15];
    float* out = (float*)d_out;

    const int* src = ei;        // edge_index[0]
    const int* dst = ei + EE;   // edge_index[1]

    void *pA, *pB, *pT, *pCnt, *pPool, *pAlloc;
    cudaGetSymbolAddress(&pA, g_bufA);
    cudaGetSymbolAddress(&pB, g_bufB);
    cudaGetSymbolAddress(&pT, g_tmp);
    cudaGetSymbolAddress(&pCnt, g_cnt);
    cudaGetSymbolAddress(&pPool, g_pool);
    cudaGetSymbolAddress(&pAlloc, g_alloc);
    float* bufA = (float*)pA;
    float* bufB = (float*)pB;
    float* tmp  = (float*)pT;

    const int AGG_GRID  = (NN + 3) / 4;
    const int GEMM_GRID = (NN + 255) / 256;

    cudaMemsetAsync(pCnt, 0, NN * sizeof(int));
    cudaMemsetAsync(pPool, 0, GG * FDIM * sizeof(unsigned));
    cudaMemsetAsync(pAlloc, 0, sizeof(int));

    // CSR build
    hist_k<<<(EE + 255) / 256, 256>>>(dst);
    alloc_k<<<(NN + 255) / 256, 256>>>();
    bin_k<<<(EE + 255) / 256, 256>>>(src, dst);

    // layer 1 (aggregate-first): tmp = A_norm @ x ; bufA = relu(tmp@W1+b1)
    agg44_k<false><<<AGG_GRID, 128>>>(x, nullptr, tmp, nullptr);
    gemm2_k<44, 44, 44, true><<<dim3(GEMM_GRID, 1), 256>>>(tmp, W1, b1, bufA);

    // layer 2 (aggregate-first): tmp = A_norm @ bufA ; bufB = relu(tmp@W2+b2)
    agg44_k<false><<<AGG_GRID, 128>>>(bufA, nullptr, tmp, nullptr);
    gemm2_k<44, 88, 44, true><<<dim3(GEMM_GRID, 2), 256>>>(tmp, W2, b2, bufB);

    // layer 3 (transform-first): tmp = bufB@W3 ; pool(relu(A_norm@tmp + b3))
    gemm2_k<88, 44, 44, false><<<dim3(GEMM_GRID, 1), 256>>>(bufB, W3, nullptr, tmp);
    agg44_k<true><<<AGG_GRID, 128>>>(tmp, b3, nullptr, batch);

    // heads
    final_k<<<GG / 8, 256>>>(feature, Wg, bg, Wf1, bf1, Wf2, bf2, out);
}